// round 5
// baseline (speedup 1.0000x reference)
#include <cuda_runtime.h>
#include <cuda_fp16.h>

// Signature-kernel MMD. ILP-2: one warp carries TWO independent path-pair tasks,
// interleaved instruction-by-instruction so each stream's SHFL/LDS latency is
// hidden under the other stream's issue slots (grid 2080 tasks = only 14
// warps/SM, so TLP can't hide it; ILP must). fp16 eps table (eps = 0.25*inc),
// row stride 68 halves -> conflict-free LDS. Masking-free Goursat wavefront.

#define BSZ 32
#define LEN 64
#define NTRI ((BSZ*(BSZ+1))/2)     // 528
#define NTASKS (2*NTRI + BSZ*BSZ)  // 2080
#define NBLK (NTASKS / 2)          // 1040 CTAs, 1 warp, 2 tasks each

#define RSH 68                     // row stride in halves
#define GUARDH 8
#define OSZH (31*RSH)
#define ESZH (32*RSH)
#define WHALVES (GUARDH + OSZH + ESZH + 4)   // 4296 halves = 8592 B per stream

__device__ float g_partial[NTASKS];
__device__ unsigned int g_count;   // zero-init; reducer re-arms

__device__ __forceinline__ void decode_task(int t, const float* x, const float* y,
                                            const float*& pa, const float*& pb,
                                            float& weight)
{
    if (t < 2*NTRI) {
        const float* base = (t < NTRI) ? x : y;
        if (t >= NTRI) t -= NTRI;
        int a = 0;
        while (t >= (BSZ - a)) { t -= (BSZ - a); ++a; }
        int b = a + t;
        pa = base + a*(LEN*4);
        pb = base + b*(LEN*4);
        weight = (a == b ? 1.0f : 2.0f) * (1.0f/1024.0f);
    } else {
        t -= 2*NTRI;
        pa = x + (t >> 5)*(LEN*4);
        pb = y + (t & 31)*(LEN*4);
        weight = -2.0f/1024.0f;
    }
}

__global__ void __launch_bounds__(32)
sig_kernel(const float* __restrict__ x, const float* __restrict__ y,
           float* __restrict__ out)
{
    extern __shared__ __align__(16) char smem[];
    const int lane = threadIdx.x & 31;

    __half* base0 = reinterpret_cast<__half*>(smem);
    __half* base1 = base0 + WHALVES;
    __half* Ob[2] = { base0 + GUARDH, base1 + GUARDH };
    __half* Eb[2] = { Ob[0] + OSZH,   Ob[1] + OSZH };

    // Zero both regions + guards: all stray PDE reads must be finite.
    {
        uint4* z = reinterpret_cast<uint4*>(smem);
        #pragma unroll
        for (int i = lane; i < (2*WHALVES*2)/16; i += 32)
            z[i] = make_uint4(0u, 0u, 0u, 0u);
    }

    // ---- decode the two tasks ----
    const float *pa[2], *pb[2];
    float wgt[2];
    decode_task(blockIdx.x*2 + 0, x, y, pa[0], pb[0], wgt[0]);
    decode_task(blockIdx.x*2 + 1, x, y, pa[1], pb[1], wgt[1]);

    // ---- streaming RBF gram + second differences -> eps (fp16), 2 streams ----
    const int j0 = lane << 1;
    float4 b0[2], b1[2];
    float g0p[2], g1p[2];
    #pragma unroll
    for (int s = 0; s < 2; ++s) {
        b0[s] = __ldg(reinterpret_cast<const float4*>(pb[s] + 4*j0));
        b1[s] = __ldg(reinterpret_cast<const float4*>(pb[s] + 4*j0 + 4));
        float4 a = __ldg(reinterpret_cast<const float4*>(pa[s]));
        float d0x=a.x-b0[s].x, d0y=a.y-b0[s].y, d0z=a.z-b0[s].z, d0w=a.w-b0[s].w;
        float d1x=a.x-b1[s].x, d1y=a.y-b1[s].y, d1z=a.z-b1[s].z, d1w=a.w-b1[s].w;
        g0p[s] = __expf(-0.5f*(d0x*d0x + d0y*d0y + d0z*d0z + d0w*d0w));
        g1p[s] = __expf(-0.5f*(d1x*d1x + d1y*d1y + d1z*d1z + d1w*d1w));
    }
    #pragma unroll 2
    for (int u = 1; u < LEN; ++u) {
        int v = u - 1;
        int rowidx = (v >> 1) * RSH;
        bool odd = (v & 1);
        #pragma unroll
        for (int s = 0; s < 2; ++s) {
            float4 a = __ldg(reinterpret_cast<const float4*>(pa[s] + 4*u));
            float d0x=a.x-b0[s].x, d0y=a.y-b0[s].y, d0z=a.z-b0[s].z, d0w=a.w-b0[s].w;
            float d1x=a.x-b1[s].x, d1y=a.y-b1[s].y, d1z=a.z-b1[s].z, d1w=a.w-b1[s].w;
            float g0 = __expf(-0.5f*(d0x*d0x + d0y*d0y + d0z*d0z + d0w*d0w));
            float g1 = __expf(-0.5f*(d1x*d1x + d1y*d1y + d1z*d1z + d1w*d1w));
            float t0 = g0 - g0p[s];
            float t1 = g1 - g1p[s];
            float tn = __shfl_down_sync(0xffffffffu, t0, 1);
            float e0 = 0.25f * (t1 - t0);
            float e1 = 0.25f * (tn - t1);
            __half* row = (odd ? Ob[s] : Eb[s]) + rowidx;
            reinterpret_cast<__half2*>(row)[lane] = __floats2half2_rn(e0, e1);
            g0p[s] = g0; g1p[s] = g1;
        }
    }
    __syncwarp();

    // ---- Goursat PDE, antidiagonal wavefront, 2 interleaved streams ----
    const int L = lane;
    const bool isL0 = (L == 0);
    const __half *p0[2], *p1[2], *p2[2], *p3[2];
    float A0[2], A1[2], A2[2], A3[2], B0[2], B1[2], B2[2], B3[2];
    #pragma unroll
    for (int s = 0; s < 2; ++s) {
        p0[s] = Ob[s] + ((L == 0) ? 0 : (66*L - 68));
        p1[s] = Eb[s] + 66*L;
        p2[s] = Eb[s] + 66*L - 1;
        p3[s] = Ob[s] + 66*L - 1;
        A0[s] = isL0 ? 1.f : 0.f; A1[s] = 0.f; A2[s] = 0.f; A3[s] = 0.f;
        B0[s] = A0[s]; B1[s] = A0[s]; B2[s] = 0.f; B3[s] = 0.f;
    }

    #pragma unroll 4
    for (int m = 0; m < 125; ++m) {
        float sh1[2], sh2[2], v3s[2];
        float a0A[2], a0B[2], a1[2], a2[2], a3[2];
        #pragma unroll
        for (int s = 0; s < 2; ++s) {
            sh1[s] = __shfl_up_sync(0xffffffffu, B3[s], 1);
            sh2[s] = __shfl_up_sync(0xffffffffu, A3[s], 1);
            a0A[s] = __half2float(p0[s][m])   - 1.0f;
            a0B[s] = __half2float(p0[s][m+1]) - 1.0f;
            a1[s]  = __half2float(p1[s][m])   - 1.0f;
            a2[s]  = __half2float(p2[s][m])   - 1.0f;
            a3[s]  = __half2float(p3[s][m])   - 1.0f;
        }
        #pragma unroll
        for (int s = 0; s < 2; ++s) {
            // diag d = 2m+2
            float v0 = fmaf(sh2[s], a0A[s], sh1[s]) + B0[s];  if (isL0) v0 = 1.f;
            float v1 = fmaf(A0[s], a1[s], B0[s]) + B1[s];
            float v2 = fmaf(A1[s], a2[s], B1[s]) + B2[s];
            float v3 = fmaf(A2[s], a3[s], B2[s]) + B3[s];
            v3s[s] = v3;
            A0[s] = v0; A1[s] = v1; A2[s] = v2; A3[s] = v3;
        }
        #pragma unroll
        for (int s = 0; s < 2; ++s) {
            float sh1b = __shfl_up_sync(0xffffffffu, v3s[s], 1);
            // diag d+1 = 2m+3 (A* now holds diag d values, B* holds diag d-1)
            float w0 = fmaf(sh1[s], a0B[s], sh1b) + A0[s]; if (isL0) w0 = 1.f;
            float w1 = fmaf(B0[s], a1[s], A0[s]) + A1[s];
            float w2 = fmaf(B1[s], a1[s], A1[s]) + A2[s];
            float w3 = fmaf(B2[s], a3[s], A2[s]) + A3[s];
            // rotate: old A (diag d) -> B-role next iter handled by swap
            float t0 = A0[s], t1 = A1[s], t2 = A2[s], t3 = A3[s];
            A0[s] = t0; A1[s] = t1; A2[s] = t2; A3[s] = t3;  // diag d -> "A"
            B0[s] = w0; B1[s] = w1; B2[s] = w2; B3[s] = w3;  // diag d+1 -> "B"
        }
    }
    // final diag 252: only cell k=2 on lane 31 (i=126, j=126)
    #pragma unroll
    for (int s = 0; s < 2; ++s) {
        float a2f = __half2float(p2[s][125]) - 1.0f;
        float f2 = fmaf(A1[s], a2f, B1[s]) + B2[s];
        float res = __shfl_sync(0xffffffffu, f2, 31);
        if (lane == 0) g_partial[blockIdx.x*2 + s] = res * wgt[s];
    }

    // ---- last-block deterministic reduction (single warp) ----
    __threadfence();
    __syncwarp();
    unsigned int ticket = 0;
    if (lane == 0) ticket = atomicAdd(&g_count, 1u);
    ticket = __shfl_sync(0xffffffffu, ticket, 0);
    if (ticket == (unsigned)(gridDim.x - 1)) {
        double s = 0.0;
        for (int i = lane; i < NTASKS; i += 32)
            s += (double)__ldcg(&g_partial[i]);
        #pragma unroll
        for (int w = 16; w > 0; w >>= 1)
            s += __shfl_down_sync(0xffffffffu, s, w);
        if (lane == 0) {
            out[0] = (float)s;
            g_count = 0;                 // re-arm for next graph replay
        }
    }
}

extern "C" void kernel_launch(void* const* d_in, const int* in_sizes, int n_in,
                              void* d_out, int out_size)
{
    const float* x = (const float*)d_in[0];
    const float* y = (const float*)d_in[1];
    (void)in_sizes; (void)n_in; (void)out_size;

    cudaFuncSetAttribute(sig_kernel,
                         cudaFuncAttributePreferredSharedMemoryCarveout, 100);

    const size_t shmem = (size_t)2 * WHALVES * sizeof(__half);  // 17184 B
    sig_kernel<<<NBLK, 32, shmem>>>(x, y, (float*)d_out);
}

// round 6
// speedup vs baseline: 1.3022x; 1.3022x over previous
#include <cuda_runtime.h>
#include <cuda_fp16.h>

// Signature-kernel MMD. R4 structure (2 warps/CTA, 14 warps/SM, one wave) with
// a carried-operand PDE loop: a2(m)=a1(m-1), a0A(m)=a0B(m-1), sh2(m)=sh1b(m-1)
// => 3 LDS + 2 SHFL per 2 diagonals (was 5 + 3). fp16 eps table (eps=0.25*inc),
// row stride 68 halves -> conflict-free LDS. Masking-free Goursat wavefront.

#define BSZ 32
#define LEN 64
#define NTRI ((BSZ*(BSZ+1))/2)     // 528
#define NTASKS (2*NTRI + BSZ*BSZ)  // 2080
#define WPC 2
#define NBLK (NTASKS / WPC)        // 1040

#define RSH 68                     // row stride in halves
#define GUARDH 8
#define OSZH (31*RSH)              // odd coarse rows 1,3,..,61
#define ESZH (32*RSH)              // even coarse rows 0,2,..,62
#define WHALVES (GUARDH + OSZH + ESZH + 4)   // 4296 halves = 8592 B / task

__device__ float g_partial[NTASKS];
__device__ unsigned int g_count;   // zero-init; reducer re-arms

__global__ void __launch_bounds__(32*WPC)
sig_kernel(const float* __restrict__ x, const float* __restrict__ y,
           float* __restrict__ out)
{
    extern __shared__ __align__(16) char smem[];
    const int lane = threadIdx.x & 31;
    const int wid  = threadIdx.x >> 5;
    const int task = blockIdx.x * WPC + wid;

    __half* warpbase = reinterpret_cast<__half*>(smem) + wid * WHALVES;
    __half* Ob = warpbase + GUARDH;
    __half* Eb = Ob + OSZH;

    // Zero own region + guard: all stray PDE reads must be finite.
    {
        uint4* z = reinterpret_cast<uint4*>(warpbase);
        #pragma unroll
        for (int i = lane; i < (WHALVES*2)/16; i += 32)
            z[i] = make_uint4(0u, 0u, 0u, 0u);
    }

    // ---- decode task -> pair pointers + weight ----
    const float *pa, *pb;
    float weight;
    {
        int t = task;
        if (t < 2*NTRI) {
            const float* base = (t < NTRI) ? x : y;
            if (t >= NTRI) t -= NTRI;
            int a = 0;
            while (t >= (BSZ - a)) { t -= (BSZ - a); ++a; }
            int b = a + t;
            pa = base + a*(LEN*4);
            pb = base + b*(LEN*4);
            weight = (a == b ? 1.0f : 2.0f) * (1.0f/1024.0f);
        } else {
            t -= 2*NTRI;
            pa = x + (t >> 5)*(LEN*4);
            pb = y + (t & 31)*(LEN*4);
            weight = -2.0f/1024.0f;
        }
    }

    // ---- streaming RBF gram + second differences -> eps = 0.25*inc (fp16) ----
    const int j0 = lane << 1;
    const float4 b0 = __ldg(reinterpret_cast<const float4*>(pb + 4*j0));
    const float4 b1 = __ldg(reinterpret_cast<const float4*>(pb + 4*j0 + 4));

    float g0p, g1p;
    {
        float4 a = __ldg(reinterpret_cast<const float4*>(pa));
        float d0x=a.x-b0.x, d0y=a.y-b0.y, d0z=a.z-b0.z, d0w=a.w-b0.w;
        float d1x=a.x-b1.x, d1y=a.y-b1.y, d1z=a.z-b1.z, d1w=a.w-b1.w;
        g0p = __expf(-0.5f*(d0x*d0x + d0y*d0y + d0z*d0z + d0w*d0w));
        g1p = __expf(-0.5f*(d1x*d1x + d1y*d1y + d1z*d1z + d1w*d1w));
    }
    #pragma unroll 4
    for (int u = 1; u < LEN; ++u) {
        float4 a = __ldg(reinterpret_cast<const float4*>(pa + 4*u));
        float d0x=a.x-b0.x, d0y=a.y-b0.y, d0z=a.z-b0.z, d0w=a.w-b0.w;
        float d1x=a.x-b1.x, d1y=a.y-b1.y, d1z=a.z-b1.z, d1w=a.w-b1.w;
        float g0 = __expf(-0.5f*(d0x*d0x + d0y*d0y + d0z*d0z + d0w*d0w));
        float g1 = __expf(-0.5f*(d1x*d1x + d1y*d1y + d1z*d1z + d1w*d1w));
        float t0 = g0 - g0p;
        float t1 = g1 - g1p;
        float tn = __shfl_down_sync(0xffffffffu, t0, 1);   // diff at col j0+2
        float e0 = 0.25f * (t1 - t0);
        float e1 = 0.25f * (tn - t1);
        int v = u - 1;
        __half* row = ((v & 1) ? Ob : Eb) + (v >> 1) * RSH;
        reinterpret_cast<__half2*>(row)[lane] = __floats2half2_rn(e0, e1);
        g0p = g0; g1p = g1;
    }
    __syncwarp();

    // ---- Goursat PDE, antidiagonal wavefront, carried-operand loop ----
    // Lane holds cells i = 4*lane + k. Carried across iterations:
    //   a0A(m) = a0B(m-1)   [p0[m]   == p0[(m-1)+1]]
    //   a2(m)  = a1(m-1)    [p2[m]   == p1[m-1]]
    //   sh2(m) = sh1b(m-1)  [shfl(A3 at m) == shfl(v3 of m-1)]
    const int L = lane;
    const bool isL0 = (L == 0);
    const __half* p0 = Ob + ((L == 0) ? 0 : (66*L - 68));
    const __half* p1 = Eb + 66*L;
    const __half* p2 = Eb + 66*L - 1;
    const __half* p3 = Ob + 66*L - 1;

    float A0 = isL0 ? 1.f : 0.f, A1 = 0.f, A2 = 0.f, A3 = 0.f;   // diag 0
    float B0 = A0, B1 = A0, B2 = 0.f, B3 = 0.f;                  // diag 1

    float a0A = __half2float(p0[0]) - 1.0f;
    float a2  = __half2float(p2[0]) - 1.0f;
    float sh2 = 0.0f;                       // shfl(A3_init) == 0 everywhere

    #pragma unroll 5
    for (int m = 0; m < 125; ++m) {
        float sh1 = __shfl_up_sync(0xffffffffu, B3, 1);
        float a0B = __half2float(p0[m+1]) - 1.0f;
        float a1  = __half2float(p1[m])   - 1.0f;
        float a3  = __half2float(p3[m])   - 1.0f;
        // diag d = 2m+2
        float v0 = fmaf(sh2, a0A, sh1) + B0;  if (isL0) v0 = 1.f;
        float v1 = fmaf(A0, a1, B0) + B1;
        float v2 = fmaf(A1, a2, B1) + B2;
        float v3 = fmaf(A2, a3, B2) + B3;
        // diag d+1 = 2m+3
        float sh1b = __shfl_up_sync(0xffffffffu, v3, 1);
        float w0 = fmaf(sh1, a0B, sh1b) + v0; if (isL0) w0 = 1.f;
        float w1 = fmaf(B0, a1, v0) + v1;
        float w2 = fmaf(B1, a1, v1) + v2;
        float w3 = fmaf(B2, a3, v2) + v3;
        A0 = v0; A1 = v1; A2 = v2; A3 = v3;
        B0 = w0; B1 = w1; B2 = w2; B3 = w3;
        a0A = a0B; a2 = a1; sh2 = sh1b;     // carry
    }
    // final diag 252: only cell k=2 on lane 31 (i=126, j=126).
    // Needs inc at p2[125] == p1[124] == carried a2.
    float f2 = fmaf(A1, a2, B1) + B2;
    float res = __shfl_sync(0xffffffffu, f2, 31);
    if (lane == 0) g_partial[task] = res * weight;

    // ---- last-block deterministic reduction ----
    __threadfence();
    __syncthreads();
    __shared__ unsigned int sticket;
    if (threadIdx.x == 0) sticket = atomicAdd(&g_count, 1u);
    __syncthreads();
    if (sticket == (unsigned)(gridDim.x - 1)) {
        double s = 0.0;
        for (int i = threadIdx.x; i < NTASKS; i += 32*WPC)
            s += (double)__ldcg(&g_partial[i]);
        double* ds = reinterpret_cast<double*>(smem);
        ds[threadIdx.x] = s;
        __syncthreads();
        for (int w = (32*WPC)/2; w > 0; w >>= 1) {
            if (threadIdx.x < w) ds[threadIdx.x] += ds[threadIdx.x + w];
            __syncthreads();
        }
        if (threadIdx.x == 0) {
            out[0] = (float)ds[0];
            g_count = 0;                 // re-arm for next graph replay
        }
    }
}

extern "C" void kernel_launch(void* const* d_in, const int* in_sizes, int n_in,
                              void* d_out, int out_size)
{
    const float* x = (const float*)d_in[0];
    const float* y = (const float*)d_in[1];
    (void)in_sizes; (void)n_in; (void)out_size;

    cudaFuncSetAttribute(sig_kernel,
                         cudaFuncAttributePreferredSharedMemoryCarveout, 100);

    const size_t shmem = (size_t)WPC * WHALVES * sizeof(__half);  // 17184 B
    sig_kernel<<<NBLK, 32*WPC, shmem>>>(x, y, (float*)d_out);
}